// round 2
// baseline (speedup 1.0000x reference)
#include <cuda_runtime.h>
#include <cuda_bf16.h>

#define NN 384
#define CC 128
#define HH 128
#define MM (384*384)   // 147456

// ---------------- scratch (device globals; no allocation allowed) ----------------
__device__ float g_left [(size_t)HH*MM];   // [h][i*384+k]  (tf32-rounded)
__device__ float g_right[(size_t)HH*MM];   // [h][k*384+j]  (tf32-rounded)
__device__ float g_gate [(size_t)HH*MM];   // [h][i*384+j]; pass2 overwrites in-place with gated out
__device__ float g_Wlr[CC*256];            // [c][h2]: 0..127 = g_left⊙W_l, 128..255 = g_right⊙W_r (tf32)
__device__ float g_blr[256];
__device__ float g_Wge[CC*256];            // [c][h2]: 0..127 = W_g, 128..255 = W_e (tf32)
__device__ float g_bge[256];

// ---------------- helpers ----------------
__device__ __forceinline__ float to_tf32(float x){
    float r; asm("cvt.rna.tf32.f32 %0, %1;" : "=f"(r) : "f"(x)); return r;
}

__device__ __forceinline__ void mma8(float* d, float a0,float a1,float a2,float a3,
                                     float b0,float b1){
    asm volatile(
      "mma.sync.aligned.m16n8k8.row.col.f32.tf32.tf32.f32 "
      "{%0,%1,%2,%3},{%4,%5,%6,%7},{%8,%9},{%0,%1,%2,%3};\n"
      : "+f"(d[0]),"+f"(d[1]),"+f"(d[2]),"+f"(d[3])
      : "r"(__float_as_uint(a0)),"r"(__float_as_uint(a1)),
        "r"(__float_as_uint(a2)),"r"(__float_as_uint(a3)),
        "r"(__float_as_uint(b0)),"r"(__float_as_uint(b1)));
}

__device__ __forceinline__ void cp16(float* s, const float* g){
    unsigned sa = (unsigned)__cvta_generic_to_shared(s);
    asm volatile("cp.async.ca.shared.global [%0], [%1], 16;" :: "r"(sa), "l"(g));
}

// ---------------- prep: fold LN affine into weights, cvt to tf32 ----------------
__global__ void prep_kernel(const float* __restrict__ Wl, const float* __restrict__ bl,
                            const float* __restrict__ Wr, const float* __restrict__ br,
                            const float* __restrict__ Wg, const float* __restrict__ bg,
                            const float* __restrict__ We, const float* __restrict__ be,
                            const float* __restrict__ gl, const float* __restrict__ bL,
                            const float* __restrict__ gr, const float* __restrict__ bR){
    int h = threadIdx.x;                 // 0..255
    if (h < 128){
        float acc = bl[h];
        for (int c = 0; c < 128; c++){
            g_Wlr[c*256 + h] = to_tf32(gl[c] * Wl[c*128 + h]);
            acc += bL[c] * Wl[c*128 + h];
        }
        g_blr[h] = acc;
        for (int c = 0; c < 128; c++) g_Wge[c*256 + h] = to_tf32(Wg[c*128 + h]);
        g_bge[h] = bg[h];
    } else {
        int hh = h - 128;
        float acc = br[hh];
        for (int c = 0; c < 128; c++){
            g_Wlr[c*256 + h] = to_tf32(gr[c] * Wr[c*128 + hh]);
            acc += bR[c] * Wr[c*128 + hh];
        }
        g_blr[h] = acc;
        for (int c = 0; c < 128; c++) g_Wge[c*256 + h] = to_tf32(We[c*128 + hh]);
        g_bge[h] = be[hh];
    }
}

// ---------------- kernel 1: LN + 4 projections + transposed store ----------------
// Block: 64 rows × full C. 256 threads = 8 warps (2x4), warp tile 32x32, micro 2x4 mmas.
// smem: xs[64][132], xn[64][132], wb union { Bs[32][136] , stage[64][133] }  (8704 floats)
#define K1_SMEM ((2*64*132 + 8704)*4)

__device__ __forceinline__ void proj_gemm(const float* __restrict__ gW, int colbase,
                                          const float* __restrict__ A,  // smem [64][132] (full K)
                                          float* __restrict__ Bs,       // smem [32][136]
                                          float (&acc)[2][4][4],
                                          int t, int wm, int wn, int gq, int tg){
    for (int kk = 0; kk < 128; kk += 32){
        __syncthreads();
        // load B chunk 32x128 (tf32 already)
        for (int p = 0; p < 4; p++){
            int idx = t + p*256;
            int c4 = idx & 31, k = idx >> 5;
            float4 v = *(const float4*)&gW[(size_t)(kk + k)*256 + colbase + c4*4];
            *(float4*)&Bs[k*136 + c4*4] = v;
        }
        __syncthreads();
        for (int ks = 0; ks < 4; ks++){
            float a[2][4];
            #pragma unroll
            for (int mm = 0; mm < 2; mm++){
                const float* ap = &A[(wm*32 + mm*16 + gq)*132 + kk + ks*8 + tg];  // FIX: + kk
                a[mm][0] = ap[0];       a[mm][1] = ap[8*132];
                a[mm][2] = ap[4];       a[mm][3] = ap[8*132 + 4];
            }
            #pragma unroll
            for (int nn = 0; nn < 4; nn++){
                const float* bp = &Bs[(ks*8 + tg)*136 + wn*32 + nn*8 + gq];
                float b0 = bp[0], b1 = bp[4*136];
                #pragma unroll
                for (int mm = 0; mm < 2; mm++)
                    mma8(acc[mm][nn], a[mm][0],a[mm][1],a[mm][2],a[mm][3], b0, b1);
            }
        }
    }
}

__device__ __forceinline__ void store_transposed(float* __restrict__ dst,
                                                 const float* __restrict__ stage,
                                                 int r0, int t){
    for (int p = 0; p < 32; p++){
        int idx = t + p*256;
        int m = idx & 63, h = idx >> 6;
        dst[(size_t)h*MM + r0 + m] = stage[m*133 + h];
    }
}

__global__ __launch_bounds__(256)
void k1_proj(const float* __restrict__ pair){
    extern __shared__ float sm[];
    float* xs = sm;                 // 64*132
    float* xn = sm + 64*132;        // 64*132
    float* wb = sm + 2*64*132;      // 8704 floats

    int t = threadIdx.x;
    int r0 = blockIdx.x * 64;
    int lane = t & 31, warp = t >> 5;
    int gq = lane >> 2, tg = lane & 3;
    int wm = warp >> 2, wn = warp & 3;

    // load + tf32-round pair tile
    for (int p = 0; p < 8; p++){
        int idx = t + p*256;
        int c4 = idx & 31, m = idx >> 5;
        float4 v = *(const float4*)&pair[(size_t)(r0 + m)*128 + c4*4];
        v.x = to_tf32(v.x); v.y = to_tf32(v.y); v.z = to_tf32(v.z); v.w = to_tf32(v.w);
        *(float4*)&xs[m*132 + c4*4] = v;
    }
    __syncthreads();

    // LayerNorm stats per row (each warp owns 8 rows)
    for (int rr = 0; rr < 8; rr++){
        int m = warp*8 + rr;
        float s = 0.f, ss = 0.f;
        #pragma unroll
        for (int q = 0; q < 4; q++){ float v = xs[m*132 + lane + q*32]; s += v; ss += v*v; }
        #pragma unroll
        for (int o = 16; o > 0; o >>= 1){ s += __shfl_xor_sync(~0u, s, o); ss += __shfl_xor_sync(~0u, ss, o); }
        float mean = s * (1.f/128.f);
        float var  = ss * (1.f/128.f) - mean*mean;
        float inv  = rsqrtf(var + 1e-5f);
        #pragma unroll
        for (int q = 0; q < 4; q++){
            int c = lane + q*32;
            xn[m*132 + c] = to_tf32((xs[m*132 + c] - mean) * inv);
        }
    }
    __syncthreads();

    float acc[2][4][4];
    float* Bs = wb;
    float* stage = wb;

    // ---- LEFT = xn@W'_l + x@W_e + biases ----
    #pragma unroll
    for (int a=0;a<2;a++) for (int b=0;b<4;b++) for (int c=0;c<4;c++) acc[a][b][c]=0.f;
    proj_gemm(g_Wlr,   0, xn, Bs, acc, t, wm, wn, gq, tg);
    proj_gemm(g_Wge, 128, xs, Bs, acc, t, wm, wn, gq, tg);
    __syncthreads();
    #pragma unroll
    for (int mm = 0; mm < 2; mm++) for (int nn = 0; nn < 4; nn++){
        int row = wm*32 + mm*16 + gq, col = wn*32 + nn*8 + 2*tg;
        float b0 = g_blr[col]   + g_bge[128 + col];
        float b1 = g_blr[col+1] + g_bge[128 + col + 1];
        stage[row*133 + col]         = to_tf32(acc[mm][nn][0] + b0);
        stage[row*133 + col + 1]     = to_tf32(acc[mm][nn][1] + b1);
        stage[(row+8)*133 + col]     = to_tf32(acc[mm][nn][2] + b0);
        stage[(row+8)*133 + col + 1] = to_tf32(acc[mm][nn][3] + b1);
    }
    __syncthreads();
    store_transposed(g_left, stage, r0, t);

    // ---- RIGHT = xn@W'_r + bias ----
    #pragma unroll
    for (int a=0;a<2;a++) for (int b=0;b<4;b++) for (int c=0;c<4;c++) acc[a][b][c]=0.f;
    proj_gemm(g_Wlr, 128, xn, Bs, acc, t, wm, wn, gq, tg);
    __syncthreads();
    #pragma unroll
    for (int mm = 0; mm < 2; mm++) for (int nn = 0; nn < 4; nn++){
        int row = wm*32 + mm*16 + gq, col = wn*32 + nn*8 + 2*tg;
        float b0 = g_blr[128 + col], b1 = g_blr[128 + col + 1];
        stage[row*133 + col]         = to_tf32(acc[mm][nn][0] + b0);
        stage[row*133 + col + 1]     = to_tf32(acc[mm][nn][1] + b1);
        stage[(row+8)*133 + col]     = to_tf32(acc[mm][nn][2] + b0);
        stage[(row+8)*133 + col + 1] = to_tf32(acc[mm][nn][3] + b1);
    }
    __syncthreads();
    store_transposed(g_right, stage, r0, t);

    // ---- GATE = sigmoid(x@W_g + bias) ----
    #pragma unroll
    for (int a=0;a<2;a++) for (int b=0;b<4;b++) for (int c=0;c<4;c++) acc[a][b][c]=0.f;
    proj_gemm(g_Wge, 0, xs, Bs, acc, t, wm, wn, gq, tg);
    __syncthreads();
    #pragma unroll
    for (int mm = 0; mm < 2; mm++) for (int nn = 0; nn < 4; nn++){
        int row = wm*32 + mm*16 + gq, col = wn*32 + nn*8 + 2*tg;
        float b0 = g_bge[col], b1 = g_bge[col + 1];
        stage[row*133 + col]         = 1.f/(1.f + expf(-(acc[mm][nn][0] + b0)));
        stage[row*133 + col + 1]     = 1.f/(1.f + expf(-(acc[mm][nn][1] + b1)));
        stage[(row+8)*133 + col]     = 1.f/(1.f + expf(-(acc[mm][nn][2] + b0)));
        stage[(row+8)*133 + col + 1] = 1.f/(1.f + expf(-(acc[mm][nn][3] + b1)));
    }
    __syncthreads();
    store_transposed(g_gate, stage, r0, t);
}

// ---------------- kernel 2: per-h 384x384x384 GEMM, gate-mul, in-place store ----------------
// Block tile 128x128, K-chunks of 32, cp.async double buffer.
// 8 warps (2x4), warp tile 64x32, micro 4x4.
#define K2_SMEM ((2*128*36 + 2*32*136)*4)

__global__ __launch_bounds__(256)
void k2_tri(){
    extern __shared__ float sm[];
    float* As = sm;                  // 2 * 128*36
    float* Bs = sm + 2*128*36;       // 2 * 32*136

    int t = threadIdx.x;
    int lane = t & 31, warp = t >> 5;
    int gq = lane >> 2, tg = lane & 3;
    int wm = warp >> 2, wn = warp & 3;

    int h  = blockIdx.z;
    int i0 = blockIdx.y * 128, j0 = blockIdx.x * 128;
    const float* L = g_left  + (size_t)h*MM;
    const float* R = g_right + (size_t)h*MM;

    float acc[4][4][4];
    #pragma unroll
    for (int a=0;a<4;a++) for (int b=0;b<4;b++) for (int c=0;c<4;c++) acc[a][b][c]=0.f;

    // issue chunk 0
    {
        for (int p = 0; p < 4; p++){
            int idx = t + p*256;
            int c4 = idx & 7,  m = idx >> 3;
            cp16(&As[m*36 + c4*4], &L[(size_t)(i0 + m)*384 + c4*4]);
        }
        for (int p = 0; p < 4; p++){
            int idx = t + p*256;
            int c4 = idx & 31, k = idx >> 5;
            cp16(&Bs[k*136 + c4*4], &R[(size_t)k*384 + j0 + c4*4]);
        }
        asm volatile("cp.async.commit_group;");
    }

    for (int c = 0; c < 12; c++){
        if (c + 1 < 12){
            int kk = (c + 1) * 32;
            int s  = (c + 1) & 1;
            for (int p = 0; p < 4; p++){
                int idx = t + p*256;
                int c4 = idx & 7,  m = idx >> 3;
                cp16(&As[s*128*36 + m*36 + c4*4], &L[(size_t)(i0 + m)*384 + kk + c4*4]);
            }
            for (int p = 0; p < 4; p++){
                int idx = t + p*256;
                int c4 = idx & 31, k = idx >> 5;
                cp16(&Bs[s*32*136 + k*136 + c4*4], &R[(size_t)(kk + k)*384 + j0 + c4*4]);
            }
            asm volatile("cp.async.commit_group;");
            asm volatile("cp.async.wait_group 1;");
        } else {
            asm volatile("cp.async.wait_group 0;");
        }
        __syncthreads();

        const float* Ab = &As[(c & 1)*128*36];
        const float* Bb = &Bs[(c & 1)*32*136];
        #pragma unroll
        for (int ks = 0; ks < 4; ks++){
            float a[4][4], b[4][2];
            #pragma unroll
            for (int mm = 0; mm < 4; mm++){
                const float* ap = &Ab[(wm*64 + mm*16 + gq)*36 + ks*8 + tg];
                a[mm][0] = ap[0];     a[mm][1] = ap[8*36];
                a[mm][2] = ap[4];     a[mm][3] = ap[8*36 + 4];
            }
            #pragma unroll
            for (int nn = 0; nn < 4; nn++){
                const float* bp = &Bb[(ks*8 + tg)*136 + wn*32 + nn*8 + gq];
                b[nn][0] = bp[0];  b[nn][1] = bp[4*136];
            }
            #pragma unroll
            for (int mm = 0; mm < 4; mm++)
                #pragma unroll
                for (int nn = 0; nn < 4; nn++)
                    mma8(acc[mm][nn], a[mm][0],a[mm][1],a[mm][2],a[mm][3],
                         b[nn][0], b[nn][1]);
        }
        __syncthreads();
    }

    // epilogue: multiply by gate, store tf32-rounded into the gate buffer (in place)
    float* G = g_gate + (size_t)h*MM;
    #pragma unroll
    for (int mm = 0; mm < 4; mm++) for (int nn = 0; nn < 4; nn++){
        int row = wm*64 + mm*16 + gq;
        int col = wn*32 + nn*8 + 2*tg;
        size_t b0 = (size_t)(i0 + row)*384 + j0 + col;
        float2 gv = *(float2*)&G[b0];
        float2 ov; ov.x = to_tf32(acc[mm][nn][0] * gv.x);
                   ov.y = to_tf32(acc[mm][nn][1] * gv.y);
        *(float2*)&G[b0] = ov;
        size_t b1 = b0 + (size_t)8*384;
        float2 gv2 = *(float2*)&G[b1];
        float2 ov2; ov2.x = to_tf32(acc[mm][nn][2] * gv2.x);
                    ov2.y = to_tf32(acc[mm][nn][3] * gv2.y);
        *(float2*)&G[b1] = ov2;
    }
}

// ---------------- kernel 3: out@W_o + bias + residual + final LN ----------------
// Block: 64 rows. A = gated-out gathered over h (transposed load). 8 warps 2x4, warp tile 32x32.
#define K3_SMEM ((64*36 + 32*136 + 64*133)*4)

__global__ __launch_bounds__(256)
void k3_out(const float* __restrict__ pair, const float* __restrict__ Wo,
            const float* __restrict__ bo,   const float* __restrict__ gout,
            const float* __restrict__ bout, float* __restrict__ out){
    extern __shared__ float sm[];
    float* As    = sm;                       // 64*36
    float* Bs    = sm + 64*36;               // 32*136
    float* stage = Bs + 32*136;              // 64*133

    int t = threadIdx.x;
    int r0 = blockIdx.x * 64;
    int lane = t & 31, warp = t >> 5;
    int gq = lane >> 2, tg = lane & 3;
    int wm = warp >> 2, wn = warp & 3;

    const float* O = g_gate;                 // holds gated output, tf32-rounded

    float acc[2][4][4];
    #pragma unroll
    for (int a=0;a<2;a++) for (int b=0;b<4;b++) for (int c=0;c<4;c++) acc[a][b][c]=0.f;

    for (int kk = 0; kk < 128; kk += 32){
        __syncthreads();
        // A: gather 32 h-planes x 64 rows (transpose into [m][k])
        for (int p = 0; p < 8; p++){
            int idx = t + p*256;
            int m = idx & 63, kl = idx >> 6;   // kl 0..31
            As[m*36 + kl] = O[(size_t)(kk + kl)*MM + r0 + m];
        }
        // B: W_o chunk 32x128, cvt to tf32
        for (int p = 0; p < 4; p++){
            int idx = t + p*256;
            int c4 = idx & 31, k = idx >> 5;
            float4 v = *(const float4*)&Wo[(size_t)(kk + k)*128 + c4*4];
            v.x = to_tf32(v.x); v.y = to_tf32(v.y); v.z = to_tf32(v.z); v.w = to_tf32(v.w);
            *(float4*)&Bs[k*136 + c4*4] = v;
        }
        __syncthreads();
        #pragma unroll
        for (int ks = 0; ks < 4; ks++){
            float a[2][4], b[4][2];
            #pragma unroll
            for (int mm = 0; mm < 2; mm++){
                const float* ap = &As[(wm*32 + mm*16 + gq)*36 + ks*8 + tg];
                a[mm][0] = ap[0];   a[mm][1] = ap[8*36];
                a[mm][2] = ap[4];   a[mm][3] = ap[8*36 + 4];
            }
            #pragma unroll
            for (int nn = 0; nn < 4; nn++){
                const float* bp = &Bs[(ks*8 + tg)*136 + wn*32 + nn*8 + gq];
                b[nn][0] = bp[0];  b[nn][1] = bp[4*136];
            }
            #pragma unroll
            for (int mm = 0; mm < 2; mm++)
                #pragma unroll
                for (int nn = 0; nn < 4; nn++)
                    mma8(acc[mm][nn], a[mm][0],a[mm][1],a[mm][2],a[mm][3],
                         b[nn][0], b[nn][1]);
        }
    }
    __syncthreads();

    // stage: + bias_o + residual(pair)
    #pragma unroll
    for (int mm = 0; mm < 2; mm++) for (int nn = 0; nn < 4; nn++){
        int row = wm*32 + mm*16 + gq, col = wn*32 + nn*8 + 2*tg;
        const float* pp = &pair[(size_t)(r0 + row)*128 + col];
        stage[row*133 + col]         = acc[mm][nn][0] + bo[col]   + pp[0];
        stage[row*133 + col + 1]     = acc[mm][nn][1] + bo[col+1] + pp[1];
        stage[(row+8)*133 + col]     = acc[mm][nn][2] + bo[col]   + pp[128*8];
        stage[(row+8)*133 + col + 1] = acc[mm][nn][3] + bo[col+1] + pp[128*8 + 1];
    }
    __syncthreads();

    // final LN per row (warp owns 8 rows), write coalesced
    for (int rr = 0; rr < 8; rr++){
        int m = warp*8 + rr;
        float s = 0.f, ss = 0.f;
        #pragma unroll
        for (int q = 0; q < 4; q++){ float v = stage[m*133 + lane + q*32]; s += v; ss += v*v; }
        #pragma unroll
        for (int o = 16; o > 0; o >>= 1){ s += __shfl_xor_sync(~0u, s, o); ss += __shfl_xor_sync(~0u, ss, o); }
        float mean = s * (1.f/128.f);
        float var  = ss * (1.f/128.f) - mean*mean;
        float inv  = rsqrtf(var + 1e-5f);
        #pragma unroll
        for (int q = 0; q < 4; q++){
            int c = lane + q*32;
            out[(size_t)(r0 + m)*128 + c] = (stage[m*133 + c] - mean) * inv * gout[c] + bout[c];
        }
    }
}

// ---------------- launch ----------------
extern "C" void kernel_launch(void* const* d_in, const int* in_sizes, int n_in,
                              void* d_out, int out_size){
    const float* pair   = (const float*)d_in[0];
    const float* g_l    = (const float*)d_in[1];
    const float* b_l    = (const float*)d_in[2];
    const float* g_r    = (const float*)d_in[3];
    const float* b_r    = (const float*)d_in[4];
    const float* g_o    = (const float*)d_in[5];
    const float* b_o    = (const float*)d_in[6];
    const float* W_l    = (const float*)d_in[7];
    const float* bias_l = (const float*)d_in[8];
    const float* W_r    = (const float*)d_in[9];
    const float* bias_r = (const float*)d_in[10];
    const float* W_g    = (const float*)d_in[11];
    const float* bias_g = (const float*)d_in[12];
    const float* W_e    = (const float*)d_in[13];
    const float* bias_e = (const float*)d_in[14];
    const float* W_o    = (const float*)d_in[15];
    const float* bias_o = (const float*)d_in[16];
    float* out = (float*)d_out;

    cudaFuncSetAttribute(k1_proj, cudaFuncAttributeMaxDynamicSharedMemorySize, K1_SMEM);
    cudaFuncSetAttribute(k2_tri,  cudaFuncAttributeMaxDynamicSharedMemorySize, K2_SMEM);
    cudaFuncSetAttribute(k3_out,  cudaFuncAttributeMaxDynamicSharedMemorySize, K3_SMEM);

    prep_kernel<<<1, 256>>>(W_l, bias_l, W_r, bias_r, W_g, bias_g, W_e, bias_e,
                            g_l, b_l, g_r, b_r);
    k1_proj<<<MM/64, 256, K1_SMEM>>>(pair);
    k2_tri<<<dim3(3, 3, 128), 256, K2_SMEM>>>();
    k3_out<<<MM/64, 256, K3_SMEM>>>(pair, W_o, bias_o, g_o, b_o, out);
}

// round 3
// speedup vs baseline: 1.1534x; 1.1534x over previous
#include <cuda_runtime.h>
#include <cuda_bf16.h>

#define NN 384
#define CC 128
#define HH 128
#define MM (384*384)   // 147456

// ---------------- scratch (device globals; no allocation allowed) ----------------
__device__ __align__(16) float g_left [(size_t)HH*MM];   // [h][i*384+k]  (tf32)
__device__ __align__(16) float g_right[(size_t)HH*MM];   // [h][k*384+j]  (tf32)
__device__ __align__(16) float g_gate [(size_t)HH*MM];   // [h][i*384+j]; pass2 overwrites in-place
__device__ __align__(16) float g_Wlr[CC*256];            // [c][h2]: 0..127 g_l⊙W_l, 128..255 g_r⊙W_r (tf32)
__device__ __align__(16) float g_blr[256];
__device__ __align__(16) float g_Wge[CC*256];            // [c][h2]: 0..127 W_g, 128..255 W_e (tf32)
__device__ __align__(16) float g_bge[256];
__device__ __align__(16) float g_Wo[CC*CC];              // tf32-rounded W_o [h][c]

// ---------------- helpers ----------------
__device__ __forceinline__ float to_tf32(float x){
    float r; asm("cvt.rna.tf32.f32 %0, %1;" : "=f"(r) : "f"(x)); return r;
}

__device__ __forceinline__ void mma8(float* d, float a0,float a1,float a2,float a3,
                                     float b0,float b1){
    asm volatile(
      "mma.sync.aligned.m16n8k8.row.col.f32.tf32.tf32.f32 "
      "{%0,%1,%2,%3},{%4,%5,%6,%7},{%8,%9},{%0,%1,%2,%3};\n"
      : "+f"(d[0]),"+f"(d[1]),"+f"(d[2]),"+f"(d[3])
      : "r"(__float_as_uint(a0)),"r"(__float_as_uint(a1)),
        "r"(__float_as_uint(a2)),"r"(__float_as_uint(a3)),
        "r"(__float_as_uint(b0)),"r"(__float_as_uint(b1)));
}

__device__ __forceinline__ void cp16(float* s, const float* g){
    unsigned sa = (unsigned)__cvta_generic_to_shared(s);
    asm volatile("cp.async.ca.shared.global [%0], [%1], 16;" :: "r"(sa), "l"(g) : "memory");
}
__device__ __forceinline__ void cp_commit(){ asm volatile("cp.async.commit_group;" ::: "memory"); }
__device__ __forceinline__ void cp_wait1(){ asm volatile("cp.async.wait_group 1;" ::: "memory"); }
__device__ __forceinline__ void cp_wait0(){ asm volatile("cp.async.wait_group 0;" ::: "memory"); }

// ---------------- prep: fold LN affine into weights, cvt to tf32 (256 blocks) ----------------
__global__ void prep_kernel(const float* __restrict__ Wl, const float* __restrict__ bl,
                            const float* __restrict__ Wr, const float* __restrict__ br,
                            const float* __restrict__ Wg, const float* __restrict__ bg,
                            const float* __restrict__ We, const float* __restrict__ be,
                            const float* __restrict__ gl, const float* __restrict__ bL,
                            const float* __restrict__ gr, const float* __restrict__ bR,
                            const float* __restrict__ Wo){
    __shared__ float red[4];
    int h2 = blockIdx.x;          // 0..255
    int c  = threadIdx.x;         // 0..127
    int lane = c & 31, warp = c >> 5;
    float pv;
    if (h2 < 128){
        float w = Wl[c*128 + h2];
        g_Wlr[c*256 + h2] = to_tf32(gl[c] * w);
        pv = bL[c] * w;
        g_Wge[c*256 + h2] = to_tf32(Wg[c*128 + h2]);
        g_Wo[h2*128 + c]  = to_tf32(Wo[h2*128 + c]);
    } else {
        int hh = h2 - 128;
        float w = Wr[c*128 + hh];
        g_Wlr[c*256 + h2] = to_tf32(gr[c] * w);
        pv = bR[c] * w;
        g_Wge[c*256 + h2] = to_tf32(We[c*128 + hh]);
    }
    #pragma unroll
    for (int o = 16; o > 0; o >>= 1) pv += __shfl_xor_sync(~0u, pv, o);
    if (lane == 0) red[warp] = pv;
    __syncthreads();
    if (c == 0){
        float s = red[0] + red[1] + red[2] + red[3];
        if (h2 < 128){ g_blr[h2] = bl[h2] + s;        g_bge[h2] = bg[h2]; }
        else         { g_blr[h2] = br[h2-128] + s;    g_bge[h2] = be[h2-128]; }
    }
}

// ---------------- kernel 1: LN + 4 projections + direct transposed stores ----------------
// Block: 64 rows × full C. 256 threads = 8 warps (2x4), warp tile 32x32, micro 2x4.
// smem: xs[64][132], xn[64][132], Bs double buffer 2*[32][136]
#define K1_SMEM ((2*64*132 + 2*32*136)*4)

__device__ __forceinline__ void proj_gemm_db(const float* __restrict__ gW, int colbase,
                                             const float* __restrict__ A,  // smem [64][132] (full K)
                                             float* __restrict__ Bs,       // smem 2*[32][136]
                                             float (&acc)[2][4][4],
                                             int t, int wm, int wn, int gq, int tg){
    // prefetch chunk 0
    #pragma unroll
    for (int p = 0; p < 4; p++){
        int idx = t + p*256;
        int c4 = idx & 31, k = idx >> 5;
        cp16(&Bs[k*136 + c4*4], &gW[(size_t)k*256 + colbase + c4*4]);
    }
    cp_commit();
    for (int c = 0; c < 4; c++){
        if (c < 3){
            int kk = (c + 1) * 32, s = (c + 1) & 1;
            #pragma unroll
            for (int p = 0; p < 4; p++){
                int idx = t + p*256;
                int c4 = idx & 31, k = idx >> 5;
                cp16(&Bs[s*32*136 + k*136 + c4*4], &gW[(size_t)(kk + k)*256 + colbase + c4*4]);
            }
            cp_commit();
            cp_wait1();
        } else cp_wait0();
        __syncthreads();
        const float* Bb = &Bs[(c & 1)*32*136];
        int kk = c*32;
        #pragma unroll
        for (int ks = 0; ks < 4; ks++){
            float a[2][4];
            #pragma unroll
            for (int mm = 0; mm < 2; mm++){
                const float* ap = &A[(wm*32 + mm*16 + gq)*132 + kk + ks*8 + tg];
                a[mm][0] = ap[0];       a[mm][1] = ap[8*132];
                a[mm][2] = ap[4];       a[mm][3] = ap[8*132 + 4];
            }
            #pragma unroll
            for (int nn = 0; nn < 4; nn++){
                const float* bp = &Bb[(ks*8 + tg)*136 + wn*32 + nn*8 + gq];
                float b0 = bp[0], b1 = bp[4*136];
                #pragma unroll
                for (int mm = 0; mm < 2; mm++)
                    mma8(acc[mm][nn], a[mm][0],a[mm][1],a[mm][2],a[mm][3], b0, b1);
            }
        }
        __syncthreads();
    }
}

__global__ __launch_bounds__(256)
void k1_proj(const float* __restrict__ pair){
    extern __shared__ float sm[];
    float* xs = sm;                 // 64*132
    float* xn = sm + 64*132;        // 64*132
    float* Bs = sm + 2*64*132;      // 2*32*136

    int t = threadIdx.x;
    int r0 = blockIdx.x * 64;
    int lane = t & 31, warp = t >> 5;
    int gq = lane >> 2, tg = lane & 3;
    int wm = warp >> 2, wn = warp & 3;

    // load + tf32-round pair tile
    #pragma unroll
    for (int p = 0; p < 8; p++){
        int idx = t + p*256;
        int c4 = idx & 31, m = idx >> 5;
        float4 v = *(const float4*)&pair[(size_t)(r0 + m)*128 + c4*4];
        v.x = to_tf32(v.x); v.y = to_tf32(v.y); v.z = to_tf32(v.z); v.w = to_tf32(v.w);
        *(float4*)&xs[m*132 + c4*4] = v;
    }
    __syncthreads();

    // LayerNorm stats per row (each warp owns 8 rows)
    for (int rr = 0; rr < 8; rr++){
        int m = warp*8 + rr;
        float s = 0.f, ss = 0.f;
        #pragma unroll
        for (int q = 0; q < 4; q++){ float v = xs[m*132 + lane + q*32]; s += v; ss += v*v; }
        #pragma unroll
        for (int o = 16; o > 0; o >>= 1){ s += __shfl_xor_sync(~0u, s, o); ss += __shfl_xor_sync(~0u, ss, o); }
        float mean = s * (1.f/128.f);
        float var  = ss * (1.f/128.f) - mean*mean;
        float inv  = rsqrtf(var + 1e-5f);
        #pragma unroll
        for (int q = 0; q < 4; q++){
            int c = lane + q*32;
            xn[m*132 + c] = to_tf32((xs[m*132 + c] - mean) * inv);
        }
    }
    __syncthreads();

    float acc[2][4][4];

    // ---- LEFT = xn@W'_l + x@W_e + biases ----
    #pragma unroll
    for (int a=0;a<2;a++) for (int b=0;b<4;b++) for (int c=0;c<4;c++) acc[a][b][c]=0.f;
    proj_gemm_db(g_Wlr,   0, xn, Bs, acc, t, wm, wn, gq, tg);
    proj_gemm_db(g_Wge, 128, xs, Bs, acc, t, wm, wn, gq, tg);
    #pragma unroll
    for (int mm = 0; mm < 2; mm++) for (int nn = 0; nn < 4; nn++){
        int row = r0 + wm*32 + mm*16 + gq, col = wn*32 + nn*8 + 2*tg;
        float b0 = g_blr[col]   + g_bge[128 + col];
        float b1 = g_blr[col+1] + g_bge[128 + col + 1];
        g_left[(size_t)col*MM + row]         = to_tf32(acc[mm][nn][0] + b0);
        g_left[(size_t)(col+1)*MM + row]     = to_tf32(acc[mm][nn][1] + b1);
        g_left[(size_t)col*MM + row + 8]     = to_tf32(acc[mm][nn][2] + b0);
        g_left[(size_t)(col+1)*MM + row + 8] = to_tf32(acc[mm][nn][3] + b1);
    }

    // ---- RIGHT = xn@W'_r + bias ----
    #pragma unroll
    for (int a=0;a<2;a++) for (int b=0;b<4;b++) for (int c=0;c<4;c++) acc[a][b][c]=0.f;
    proj_gemm_db(g_Wlr, 128, xn, Bs, acc, t, wm, wn, gq, tg);
    #pragma unroll
    for (int mm = 0; mm < 2; mm++) for (int nn = 0; nn < 4; nn++){
        int row = r0 + wm*32 + mm*16 + gq, col = wn*32 + nn*8 + 2*tg;
        float b0 = g_blr[128 + col], b1 = g_blr[128 + col + 1];
        g_right[(size_t)col*MM + row]         = to_tf32(acc[mm][nn][0] + b0);
        g_right[(size_t)(col+1)*MM + row]     = to_tf32(acc[mm][nn][1] + b1);
        g_right[(size_t)col*MM + row + 8]     = to_tf32(acc[mm][nn][2] + b0);
        g_right[(size_t)(col+1)*MM + row + 8] = to_tf32(acc[mm][nn][3] + b1);
    }

    // ---- GATE = sigmoid(x@W_g + bias) ----
    #pragma unroll
    for (int a=0;a<2;a++) for (int b=0;b<4;b++) for (int c=0;c<4;c++) acc[a][b][c]=0.f;
    proj_gemm_db(g_Wge, 0, xs, Bs, acc, t, wm, wn, gq, tg);
    #pragma unroll
    for (int mm = 0; mm < 2; mm++) for (int nn = 0; nn < 4; nn++){
        int row = r0 + wm*32 + mm*16 + gq, col = wn*32 + nn*8 + 2*tg;
        float b0 = g_bge[col], b1 = g_bge[col + 1];
        g_gate[(size_t)col*MM + row]         = 1.f/(1.f + expf(-(acc[mm][nn][0] + b0)));
        g_gate[(size_t)(col+1)*MM + row]     = 1.f/(1.f + expf(-(acc[mm][nn][1] + b1)));
        g_gate[(size_t)col*MM + row + 8]     = 1.f/(1.f + expf(-(acc[mm][nn][2] + b0)));
        g_gate[(size_t)(col+1)*MM + row + 8] = 1.f/(1.f + expf(-(acc[mm][nn][3] + b1)));
    }
}

// ---------------- kernel 2: per-h 384x384x384 GEMM, gate-mul, in-place store ----------------
#define K2_SMEM ((2*128*36 + 2*32*136)*4)

__global__ __launch_bounds__(256)
void k2_tri(){
    extern __shared__ float sm[];
    float* As = sm;                  // 2 * 128*36
    float* Bs = sm + 2*128*36;       // 2 * 32*136

    int t = threadIdx.x;
    int lane = t & 31, warp = t >> 5;
    int gq = lane >> 2, tg = lane & 3;
    int wm = warp >> 2, wn = warp & 3;

    int h  = blockIdx.z;
    int i0 = blockIdx.y * 128, j0 = blockIdx.x * 128;
    const float* L = g_left  + (size_t)h*MM;
    const float* R = g_right + (size_t)h*MM;

    float acc[4][4][4];
    #pragma unroll
    for (int a=0;a<4;a++) for (int b=0;b<4;b++) for (int c=0;c<4;c++) acc[a][b][c]=0.f;

    {
        for (int p = 0; p < 4; p++){
            int idx = t + p*256;
            int c4 = idx & 7,  m = idx >> 3;
            cp16(&As[m*36 + c4*4], &L[(size_t)(i0 + m)*384 + c4*4]);
        }
        for (int p = 0; p < 4; p++){
            int idx = t + p*256;
            int c4 = idx & 31, k = idx >> 5;
            cp16(&Bs[k*136 + c4*4], &R[(size_t)k*384 + j0 + c4*4]);
        }
        cp_commit();
    }

    for (int c = 0; c < 12; c++){
        if (c + 1 < 12){
            int kk = (c + 1) * 32;
            int s  = (c + 1) & 1;
            for (int p = 0; p < 4; p++){
                int idx = t + p*256;
                int c4 = idx & 7,  m = idx >> 3;
                cp16(&As[s*128*36 + m*36 + c4*4], &L[(size_t)(i0 + m)*384 + kk + c4*4]);
            }
            for (int p = 0; p < 4; p++){
                int idx = t + p*256;
                int c4 = idx & 31, k = idx >> 5;
                cp16(&Bs[s*32*136 + k*136 + c4*4], &R[(size_t)(kk + k)*384 + j0 + c4*4]);
            }
            cp_commit();
            cp_wait1();
        } else {
            cp_wait0();
        }
        __syncthreads();

        const float* Ab = &As[(c & 1)*128*36];
        const float* Bb = &Bs[(c & 1)*32*136];
        #pragma unroll
        for (int ks = 0; ks < 4; ks++){
            float a[4][4], b[4][2];
            #pragma unroll
            for (int mm = 0; mm < 4; mm++){
                const float* ap = &Ab[(wm*64 + mm*16 + gq)*36 + ks*8 + tg];
                a[mm][0] = ap[0];     a[mm][1] = ap[8*36];
                a[mm][2] = ap[4];     a[mm][3] = ap[8*36 + 4];
            }
            #pragma unroll
            for (int nn = 0; nn < 4; nn++){
                const float* bp = &Bb[(ks*8 + tg)*136 + wn*32 + nn*8 + gq];
                b[nn][0] = bp[0];  b[nn][1] = bp[4*136];
            }
            #pragma unroll
            for (int mm = 0; mm < 4; mm++)
                #pragma unroll
                for (int nn = 0; nn < 4; nn++)
                    mma8(acc[mm][nn], a[mm][0],a[mm][1],a[mm][2],a[mm][3],
                         b[nn][0], b[nn][1]);
        }
        __syncthreads();
    }

    float* G = g_gate + (size_t)h*MM;
    #pragma unroll
    for (int mm = 0; mm < 4; mm++) for (int nn = 0; nn < 4; nn++){
        int row = wm*64 + mm*16 + gq;
        int col = wn*32 + nn*8 + 2*tg;
        size_t b0 = (size_t)(i0 + row)*384 + j0 + col;
        float2 gv = *(float2*)&G[b0];
        float2 ov; ov.x = to_tf32(acc[mm][nn][0] * gv.x);
                   ov.y = to_tf32(acc[mm][nn][1] * gv.y);
        *(float2*)&G[b0] = ov;
        size_t b1 = b0 + (size_t)8*384;
        float2 gv2 = *(float2*)&G[b1];
        float2 ov2; ov2.x = to_tf32(acc[mm][nn][2] * gv2.x);
                    ov2.y = to_tf32(acc[mm][nn][3] * gv2.y);
        *(float2*)&G[b1] = ov2;
    }
}

// ---------------- kernel 3: out@W_o + bias + residual + final LN ----------------
// Block: 64 rows. A gathered k-major via cp.async (double buffered), B from g_Wo.
#define K3_SMEM ((2*32*72 + 2*32*136)*4)

__global__ __launch_bounds__(256)
void k3_out(const float* __restrict__ pair,
            const float* __restrict__ bo,   const float* __restrict__ gout,
            const float* __restrict__ bout, float* __restrict__ out){
    extern __shared__ float sm[];
    float* As    = sm;                       // 2 * 32*72   (k-major: As[kl][m], pad 72)
    float* Bs    = sm + 2*32*72;             // 2 * 32*136
    float* stage = sm;                       // reused after mainloop: 64*133

    int t = threadIdx.x;
    int r0 = blockIdx.x * 64;
    int lane = t & 31, warp = t >> 5;
    int gq = lane >> 2, tg = lane & 3;
    int wm = warp >> 2, wn = warp & 3;

    const float* O = g_gate;

    float acc[2][4][4];
    #pragma unroll
    for (int a=0;a<2;a++) for (int b=0;b<4;b++) for (int c=0;c<4;c++) acc[a][b][c]=0.f;

    // prefetch chunk 0
    #pragma unroll
    for (int p = 0; p < 2; p++){
        int idx = t + p*256;
        int kl = idx >> 4, m16 = idx & 15;
        cp16(&As[kl*72 + m16*4], &O[(size_t)kl*MM + r0 + m16*4]);
    }
    #pragma unroll
    for (int p = 0; p < 4; p++){
        int idx = t + p*256;
        int k = idx >> 5, c4 = idx & 31;
        cp16(&Bs[k*136 + c4*4], &g_Wo[(size_t)k*128 + c4*4]);
    }
    cp_commit();

    for (int c = 0; c < 4; c++){
        if (c < 3){
            int kk = (c + 1)*32, s = (c + 1) & 1;
            #pragma unroll
            for (int p = 0; p < 2; p++){
                int idx = t + p*256;
                int kl = idx >> 4, m16 = idx & 15;
                cp16(&As[s*32*72 + kl*72 + m16*4], &O[(size_t)(kk + kl)*MM + r0 + m16*4]);
            }
            #pragma unroll
            for (int p = 0; p < 4; p++){
                int idx = t + p*256;
                int k = idx >> 5, c4 = idx & 31;
                cp16(&Bs[s*32*136 + k*136 + c4*4], &g_Wo[(size_t)(kk + k)*128 + c4*4]);
            }
            cp_commit();
            cp_wait1();
        } else cp_wait0();
        __syncthreads();

        const float* Ab = &As[(c & 1)*32*72];
        const float* Bb = &Bs[(c & 1)*32*136];
        #pragma unroll
        for (int ks = 0; ks < 4; ks++){
            float a[2][4], b[4][2];
            #pragma unroll
            for (int mm = 0; mm < 2; mm++){
                const float* ap = &Ab[(ks*8 + tg)*72 + wm*32 + mm*16 + gq];
                a[mm][0] = ap[0];        a[mm][1] = ap[8];
                a[mm][2] = ap[4*72];     a[mm][3] = ap[4*72 + 8];
            }
            #pragma unroll
            for (int nn = 0; nn < 4; nn++){
                const float* bp = &Bb[(ks*8 + tg)*136 + wn*32 + nn*8 + gq];
                b[nn][0] = bp[0];  b[nn][1] = bp[4*136];
            }
            #pragma unroll
            for (int mm = 0; mm < 2; mm++)
                #pragma unroll
                for (int nn = 0; nn < 4; nn++)
                    mma8(acc[mm][nn], a[mm][0],a[mm][1],a[mm][2],a[mm][3],
                         b[nn][0], b[nn][1]);
        }
        __syncthreads();
    }

    // stage: + bias_o + residual(pair)
    #pragma unroll
    for (int mm = 0; mm < 2; mm++) for (int nn = 0; nn < 4; nn++){
        int row = wm*32 + mm*16 + gq, col = wn*32 + nn*8 + 2*tg;
        const float* pp = &pair[(size_t)(r0 + row)*128 + col];
        stage[row*133 + col]         = acc[mm][nn][0] + bo[col]   + pp[0];
        stage[row*133 + col + 1]     = acc[mm][nn][1] + bo[col+1] + pp[1];
        stage[(row+8)*133 + col]     = acc[mm][nn][2] + bo[col]   + pp[128*8];
        stage[(row+8)*133 + col + 1] = acc[mm][nn][3] + bo[col+1] + pp[128*8 + 1];
    }
    __syncthreads();

    // final LN per row (warp owns 8 rows), coalesced writes
    for (int rr = 0; rr < 8; rr++){
        int m = warp*8 + rr;
        float s = 0.f, ss = 0.f;
        #pragma unroll
        for (int q = 0; q < 4; q++){ float v = stage[m*133 + lane + q*32]; s += v; ss += v*v; }
        #pragma unroll
        for (int o = 16; o > 0; o >>= 1){ s += __shfl_xor_sync(~0u, s, o); ss += __shfl_xor_sync(~0u, ss, o); }
        float mean = s * (1.f/128.f);
        float var  = ss * (1.f/128.f) - mean*mean;
        float inv  = rsqrtf(var + 1e-5f);
        #pragma unroll
        for (int q = 0; q < 4; q++){
            int c = lane + q*32;
            out[(size_t)(r0 + m)*128 + c] = (stage[m*133 + c] - mean) * inv * gout[c] + bout[c];
        }
    }
}

// ---------------- launch ----------------
extern "C" void kernel_launch(void* const* d_in, const int* in_sizes, int n_in,
                              void* d_out, int out_size){
    const float* pair   = (const float*)d_in[0];
    const float* g_l    = (const float*)d_in[1];
    const float* b_l    = (const float*)d_in[2];
    const float* g_r    = (const float*)d_in[3];
    const float* b_r    = (const float*)d_in[4];
    const float* g_o    = (const float*)d_in[5];
    const float* b_o    = (const float*)d_in[6];
    const float* W_l    = (const float*)d_in[7];
    const float* bias_l = (const float*)d_in[8];
    const float* W_r    = (const float*)d_in[9];
    const float* bias_r = (const float*)d_in[10];
    const float* W_g    = (const float*)d_in[11];
    const float* bias_g = (const float*)d_in[12];
    const float* W_e    = (const float*)d_in[13];
    const float* bias_e = (const float*)d_in[14];
    const float* W_o    = (const float*)d_in[15];
    const float* bias_o = (const float*)d_in[16];
    float* out = (float*)d_out;

    cudaFuncSetAttribute(k1_proj, cudaFuncAttributeMaxDynamicSharedMemorySize, K1_SMEM);
    cudaFuncSetAttribute(k2_tri,  cudaFuncAttributeMaxDynamicSharedMemorySize, K2_SMEM);
    cudaFuncSetAttribute(k3_out,  cudaFuncAttributeMaxDynamicSharedMemorySize, K3_SMEM);

    prep_kernel<<<256, 128>>>(W_l, bias_l, W_r, bias_r, W_g, bias_g, W_e, bias_e,
                              g_l, b_l, g_r, b_r, W_o);
    k1_proj<<<MM/64, 256, K1_SMEM>>>(pair);
    k2_tri<<<dim3(3, 3, 128), 256, K2_SMEM>>>();
    k3_out<<<MM/64, 256, K3_SMEM>>>(pair, bias_o, g_o, b_o, out);
}